// round 2
// baseline (speedup 1.0000x reference)
#include <cuda_runtime.h>

#define B_ 16
#define D_ 128
#define L_ 4096
#define K_ 4096
#define N_ 65536          // B_*L_
#define NBLK (N_ / 64)    // 1024 main blocks

// Scratch (static device globals; no allocation)
__device__ __align__(16) float g_xn[(size_t)N_ * D_];    // normalized x, [N, D]
__device__ __align__(16) float g_cbn[(size_t)K_ * D_];   // normalized codebook, [K, D]
__device__ float g_blocksum[NBLK];

// ---------------- packed f32x2 helpers ----------------
__device__ __forceinline__ unsigned long long dup_f32(float v) {
    unsigned long long r;
    unsigned int u = __float_as_uint(v);
    asm("mov.b64 %0, {%1, %1};" : "=l"(r) : "r"(u));
    return r;
}
__device__ __forceinline__ void ffma2(unsigned long long& acc,
                                      unsigned long long a, unsigned long long b) {
    asm("fma.rn.f32x2 %0, %1, %2, %0;" : "+l"(acc) : "l"(a), "l"(b));
}
__device__ __forceinline__ void unpack2(float& lo, float& hi, unsigned long long v) {
    unsigned int a, b;
    asm("mov.b64 {%0, %1}, %2;" : "=r"(a), "=r"(b) : "l"(v));
    lo = __uint_as_float(a);
    hi = __uint_as_float(b);
}

// ---------------- kernel 1: normalize codebook ----------------
// grid 512 x 256 threads; one warp per codebook row (512*8 = 4096 rows)
__global__ void norm_cb_kernel(const float* __restrict__ cb) {
    int wid = threadIdx.x >> 5, lane = threadIdx.x & 31;
    int row = blockIdx.x * 8 + wid;
    const float4* src = (const float4*)(cb + (size_t)row * D_);
    float4 v = src[lane];
    float s = v.x * v.x + v.y * v.y + v.z * v.z + v.w * v.w;
#pragma unroll
    for (int o = 16; o; o >>= 1) s += __shfl_xor_sync(0xffffffffu, s, o);
    float inv = 1.0f / fmaxf(sqrtf(s), 1e-12f);
    float4 o4 = make_float4(v.x * inv, v.y * inv, v.z * inv, v.w * inv);
    ((float4*)(g_cbn + (size_t)row * D_))[lane] = o4;
}

// ---------------- kernel 2: transpose + normalize x ----------------
// x is [B, D, L]; one block handles 64 consecutive l for one b (all 128 d).
// grid 1024 x 256 threads.
__global__ void norm_x_kernel(const float* __restrict__ x) {
    __shared__ float s[128][65];
    __shared__ float psum[4][64];
    __shared__ float sinv[64];
    int tid = threadIdx.x;
    int b = blockIdx.x >> 6;
    int l0 = (blockIdx.x & 63) * 64;

    int lq = tid & 15;          // 16 threads per row, float4 along l
    int drow = tid >> 4;        // 16 rows per iteration
#pragma unroll
    for (int it = 0; it < 8; it++) {
        int d = it * 16 + drow;
        float4 v = *(const float4*)(x + ((size_t)(b * D_ + d)) * L_ + l0 + lq * 4);
        s[d][lq * 4 + 0] = v.x;
        s[d][lq * 4 + 1] = v.y;
        s[d][lq * 4 + 2] = v.z;
        s[d][lq * 4 + 3] = v.w;
    }
    __syncthreads();

    int t = tid & 63, g = tid >> 6;
    float p = 0.f;
#pragma unroll
    for (int dd = 0; dd < 32; dd++) {
        float v = s[g * 32 + dd][t];
        p += v * v;
    }
    psum[g][t] = p;
    __syncthreads();
    if (tid < 64) {
        float n = sqrtf(psum[0][tid] + psum[1][tid] + psum[2][tid] + psum[3][tid]);
        sinv[tid] = 1.0f / fmaxf(n, 1e-12f);
    }
    __syncthreads();

    int n0 = b * L_ + l0;
#pragma unroll
    for (int it = 0; it < 32; it++) {
        int e = it * 256 + tid;
        int tt = e >> 7, d = e & 127;
        g_xn[(size_t)(n0 + tt) * D_ + d] = s[d][tt] * sinv[tt];
    }
}

// ---------------- kernel 3: fused GEMM + argmax + output ----------------
// 64 tokens per block, 256 threads (16x16), thread tile 4 tokens x 4 codes.
// smem: xs2 = x values duplicated as (v,v) u64 pairs, [128 d][64 tok] (64KB)
//       cbs = codebook tile transposed [128 d][64 code + pad4]      (34.8KB)
#define XS2_U64   (128 * 64)                       // u64 elements
#define CBS_F32   (128 * 68)                       // f32 elements
#define SMEM_MAIN (XS2_U64 * 8 + CBS_F32 * 4)      // 100352 bytes

__global__ __launch_bounds__(256, 2) void vq_main_kernel(float* __restrict__ out) {
    extern __shared__ float sm[];
    unsigned long long* xs2 = (unsigned long long*)sm;        // [128][64] u64
    float* cbs = sm + XS2_U64 * 2;                            // [128][68] f32

    int tid = threadIdx.x;
    int tx = tid & 15, ty = tid >> 4;
    int n0 = blockIdx.x * 64;
    int b = n0 >> 12, l0 = n0 & 4095;

    // ---- load x tile once, transposed + duplicated pairs ----
    {
        int r = tid >> 2, q = tid & 3;
        const float4* src = (const float4*)g_xn + (size_t)(n0 + r) * 32;
#pragma unroll
        for (int j = 0; j < 8; j++) {
            float4 v = src[q * 8 + j];
            int d = (q * 8 + j) * 4;
            xs2[(d + 0) * 64 + r] = dup_f32(v.x);
            xs2[(d + 1) * 64 + r] = dup_f32(v.y);
            xs2[(d + 2) * 64 + r] = dup_f32(v.z);
            xs2[(d + 3) * 64 + r] = dup_f32(v.w);
        }
    }

    float best[4];
    int bidx[4];
#pragma unroll
    for (int i = 0; i < 4; i++) { best[i] = -2.0f; bidx[i] = 0; }

    int cr = tid >> 2, cq = tid & 3;

    for (int k0 = 0; k0 < K_; k0 += 64) {
        __syncthreads();   // previous tile's reads done (and xs2 visible on iter 0)
        // stream 64-code tile, transposed into smem
        const float4* csrc = (const float4*)g_cbn + (size_t)(k0 + cr) * 32;
#pragma unroll
        for (int j = 0; j < 8; j++) {
            float4 v = csrc[cq * 8 + j];
            int d = (cq * 8 + j) * 4;
            cbs[(d + 0) * 68 + cr] = v.x;
            cbs[(d + 1) * 68 + cr] = v.y;
            cbs[(d + 2) * 68 + cr] = v.z;
            cbs[(d + 3) * 68 + cr] = v.w;
        }
        __syncthreads();

        unsigned long long acc[4][2];
#pragma unroll
        for (int i = 0; i < 4; i++) { acc[i][0] = 0ull; acc[i][1] = 0ull; }

#pragma unroll 4
        for (int d = 0; d < 128; d++) {
            // code pair-packed values: (c0,c1),(c2,c3) straight from LDS.128
            ulonglong2 cbp = *(const ulonglong2*)(cbs + d * 68 + tx * 4);
            const unsigned long long* xrow = xs2 + d * 64 + ty * 4;
#pragma unroll
            for (int i = 0; i < 4; i++) {
                unsigned long long xd = xrow[i];   // (x_i, x_i) duplicated
                ffma2(acc[i][0], xd, cbp.x);
                ffma2(acc[i][1], xd, cbp.y);
            }
        }

        // running argmax (strict > keeps first occurrence; codes ascend)
        int cbase = k0 + tx * 4;
#pragma unroll
        for (int i = 0; i < 4; i++) {
            float v0, v1, v2, v3;
            unpack2(v0, v1, acc[i][0]);
            unpack2(v2, v3, acc[i][1]);
            if (v0 > best[i]) { best[i] = v0; bidx[i] = cbase + 0; }
            if (v1 > best[i]) { best[i] = v1; bidx[i] = cbase + 1; }
            if (v2 > best[i]) { best[i] = v2; bidx[i] = cbase + 2; }
            if (v3 > best[i]) { best[i] = v3; bidx[i] = cbase + 3; }
        }
    }
    __syncthreads();

    // ---- cross-thread argmax reduction (reuse smem) ----
    float* redv = cbs;                 // [64][16]
    int* redi = (int*)(cbs + 1024);    // [64][16]
#pragma unroll
    for (int i = 0; i < 4; i++) {
        int r = ty * 4 + i;
        redv[r * 16 + tx] = best[i];
        redi[r * 16 + tx] = bidx[i];
    }
    __syncthreads();

    int* s_idx = (int*)xs2;            // [64]
    float* s_val = (float*)xs2 + 64;   // [64] + 2 warp partials
    if (tid < 64) {
        float bv = redv[tid * 16];
        int bi = redi[tid * 16];
#pragma unroll
        for (int j = 1; j < 16; j++) {
            float v = redv[tid * 16 + j];
            int ii = redi[tid * 16 + j];
            if (v > bv || (v == bv && ii < bi)) { bv = v; bi = ii; }
        }
        s_idx[tid] = bi;
        s_val[tid] = bv;
    }
    __syncthreads();

    // deterministic per-block loss partial
    if (tid < 64) {
        float v = s_val[tid];
#pragma unroll
        for (int o = 16; o; o >>= 1) v += __shfl_down_sync(0xffffffffu, v, o);
        if ((tid & 31) == 0) s_val[64 + (tid >> 5)] = v;
    }
    __syncthreads();
    if (tid == 0) g_blocksum[blockIdx.x] = s_val[64] + s_val[65];

    // ---- write quantized output back in [B, D, L] layout ----
#pragma unroll
    for (int it = 0; it < 32; it++) {
        int e = it * 256 + tid;
        int t = e & 63, d = e >> 6;
        out[((size_t)(b * D_ + d)) * L_ + l0 + t] = g_cbn[(size_t)s_idx[t] * D_ + d];
    }
}

// ---------------- kernel 4: finalize loss ----------------
__global__ void finalize_kernel(float* __restrict__ out, int out_size) {
    __shared__ float red[256];
    float s = 0.f;
    for (int i = threadIdx.x; i < NBLK; i += 256) s += g_blocksum[i];
    red[threadIdx.x] = s;
    __syncthreads();
    for (int o = 128; o; o >>= 1) {
        if (threadIdx.x < o) red[threadIdx.x] += red[threadIdx.x + o];
        __syncthreads();
    }
    if (threadIdx.x == 0)
        out[out_size - 1] = 2.0f - 2.0f * red[0] / (float)N_;
}

extern "C" void kernel_launch(void* const* d_in, const int* in_sizes, int n_in,
                              void* d_out, int out_size) {
    const float* x = (const float*)d_in[0];          // [16, 128, 4096] f32
    const float* cb = (const float*)d_in[1];         // [4096, 128] f32
    float* out = (float*)d_out;

    cudaFuncSetAttribute(vq_main_kernel,
                         cudaFuncAttributeMaxDynamicSharedMemorySize, SMEM_MAIN);

    norm_cb_kernel<<<K_ / 8, 256>>>(cb);
    norm_x_kernel<<<1024, 256>>>(x);
    vq_main_kernel<<<NBLK, 256, SMEM_MAIN>>>(out);
    finalize_kernel<<<1, 256>>>(out, out_size);
}

// round 5
// speedup vs baseline: 1.0715x; 1.0715x over previous
#include <cuda_runtime.h>

#define D_ 128
#define L_ 4096
#define K_ 4096
#define N_ 65536
#define NBLK 1024            // main blocks, 64 tokens each
#define XS_F 8192            // floats per x slab: 128 d * 64 tok

typedef unsigned long long u64;
typedef unsigned int u32;

// ---- scratch (static device globals; no allocation) ----
__device__ __align__(16) float g_xt[(size_t)NBLK * XS_F];  // [blk][d][tok], normalized x
__device__ __align__(16) float g_cbn[K_ * D_];             // normalized codebook [k][d]
__device__ __align__(16) float g_cbt[D_ * K_];             // transposed  [d][k]
__device__ float g_blocksum[NBLK];
__device__ u32 g_count;

// ---- helpers ----
__device__ __forceinline__ u32 smem_u32(const void* p) {
    return (u32)__cvta_generic_to_shared(p);
}
__device__ __forceinline__ void cp16(u32 dst, const void* src) {
    asm volatile("cp.async.cg.shared.global [%0], [%1], 16;" :: "r"(dst), "l"(src) : "memory");
}
__device__ __forceinline__ void cp_commit() { asm volatile("cp.async.commit_group;" ::: "memory"); }
__device__ __forceinline__ void cp_wait1()  { asm volatile("cp.async.wait_group 1;" ::: "memory"); }
__device__ __forceinline__ void cp_wait0()  { asm volatile("cp.async.wait_group 0;" ::: "memory"); }

__device__ __forceinline__ void ffma2(u64& acc, u64 a, u64 b) {
    asm("fma.rn.f32x2 %0, %1, %2, %0;" : "+l"(acc) : "l"(a), "l"(b));
}
__device__ __forceinline__ u64 swap_pair(u64 v) {
    u64 r;
    asm("{\n\t.reg .b32 lo, hi;\n\tmov.b64 {lo, hi}, %1;\n\tmov.b64 %0, {hi, lo};\n\t}"
        : "=l"(r) : "l"(v));
    return r;
}
__device__ __forceinline__ void unpack2(float& lo, float& hi, u64 v) {
    u32 a, b;
    asm("mov.b64 {%0, %1}, %2;" : "=r"(a), "=r"(b) : "l"(v));
    lo = __uint_as_float(a); hi = __uint_as_float(b);
}

// ================= kernel 1: prep =================
// blocks [0,512): normalize codebook (8 rows/block) -> g_cbn + g_cbt
// blocks [512,1536): transpose+normalize x (64 tokens/block) -> g_xt
__global__ void prep_kernel(const float* __restrict__ x, const float* __restrict__ cb) {
    __shared__ float s[128][65];
    __shared__ float psum[4][64];
    __shared__ float sinv[64];
    int tid = threadIdx.x;
    int bid = blockIdx.x;
    if (bid == 0 && tid == 0) g_count = 0;

    if (bid < 512) {
        int wid = tid >> 5, lane = tid & 31;
        int row = bid * 8 + wid;
        float4 v = ((const float4*)(cb + (size_t)row * D_))[lane];
        float ss = v.x * v.x + v.y * v.y + v.z * v.z + v.w * v.w;
#pragma unroll
        for (int o = 16; o; o >>= 1) ss += __shfl_xor_sync(0xffffffffu, ss, o);
        float inv = 1.0f / fmaxf(sqrtf(ss), 1e-12f);
        float4 o4 = make_float4(v.x * inv, v.y * inv, v.z * inv, v.w * inv);
        ((float4*)(g_cbn + (size_t)row * D_))[lane] = o4;
        int d0 = lane * 4;
        g_cbt[(d0 + 0) * K_ + row] = o4.x;
        g_cbt[(d0 + 1) * K_ + row] = o4.y;
        g_cbt[(d0 + 2) * K_ + row] = o4.z;
        g_cbt[(d0 + 3) * K_ + row] = o4.w;
    } else {
        int xb = bid - 512;               // 0..1023, 64 tokens each
        int b = xb >> 6;
        int l0 = (xb & 63) * 64;
        int lq = tid & 15, drow = tid >> 4;
#pragma unroll
        for (int it = 0; it < 8; it++) {
            int d = it * 16 + drow;
            float4 v = *(const float4*)(x + ((size_t)(b * D_ + d)) * L_ + l0 + lq * 4);
            s[d][lq * 4 + 0] = v.x;
            s[d][lq * 4 + 1] = v.y;
            s[d][lq * 4 + 2] = v.z;
            s[d][lq * 4 + 3] = v.w;
        }
        __syncthreads();
        int t = tid & 63, g = tid >> 6;
        float p = 0.f;
#pragma unroll
        for (int dd = 0; dd < 32; dd++) { float v = s[g * 32 + dd][t]; p += v * v; }
        psum[g][t] = p;
        __syncthreads();
        if (tid < 64) {
            float n = sqrtf(psum[0][tid] + psum[1][tid] + psum[2][tid] + psum[3][tid]);
            sinv[tid] = 1.0f / fmaxf(n, 1e-12f);
        }
        __syncthreads();
        float* dst = g_xt + (size_t)xb * XS_F;
#pragma unroll
        for (int it = 0; it < 32; it++) {
            int e = it * 256 + tid;
            int d = e >> 6, tt = e & 63;
            dst[d * 64 + tt] = s[d][tt] * sinv[tt];
        }
    }
}

// ================= kernel 2: fused GEMM + argmax + output + loss =================
// block: 64 tokens x full K. 256 threads (16 tx code-groups x 16 ty token-groups).
// thread tile: 4 tokens x 8 codes via diagonal f32x2 pairs.
#define CBST 132                        // cb tile row stride in floats (128 + 4 pad)
#define CBT_F (128 * CBST)              // 16896 floats per buffer
#define SMEM_MAIN ((XS_F + 2 * CBT_F) * 4)   // 167936 bytes

// Copy one 128x128 cb tile (kt-th group of 128 codes) into a smem buffer.
// 2 threads per d-row, each copies 256 contiguous bytes (16 x cp16) = 512 B/row.
__device__ __forceinline__ void load_cb_tile(float* dst_tile, int kt, int tid) {
    int r = tid >> 1;
    int hb = (tid & 1) * 256;
    u32 dst = smem_u32(dst_tile) + r * (CBST * 4) + hb;
    const char* src = (const char*)(g_cbt + (size_t)r * K_ + (size_t)kt * 128) + hb;
#pragma unroll
    for (int i = 0; i < 16; i++) cp16(dst + i * 16, src + i * 16);
}

__global__ __launch_bounds__(256, 1) void vq_main_kernel(float* __restrict__ out, int out_size) {
    extern __shared__ float sm[];
    float* xs  = sm;                    // [128 d][64 tok]
    float* cb0 = sm + XS_F;             // [128 d][132]
    float* cb1 = sm + XS_F + CBT_F;

    int tid = threadIdx.x;
    int tx = tid & 15, ty = tid >> 4;
    int bid = blockIdx.x;

    // ---- preload x slab + cb tile 0 (one cp.async group) ----
    {
        u32 xd = smem_u32(xs);
        const char* gx = (const char*)(g_xt + (size_t)bid * XS_F);
#pragma unroll
        for (int i = 0; i < 8; i++) {
            int c = i * 256 + tid;
            cp16(xd + c * 16, gx + c * 16);
        }
        load_cb_tile(cb0, 0, tid);
        cp_commit();
    }

    float best[4] = {-2.f, -2.f, -2.f, -2.f};
    int bidx[4] = {0, 0, 0, 0};
    const char* xptr = (const char*)xs + ty * 16;   // this thread's 4 tokens

    for (int kt = 0; kt < 32; kt++) {
        float* cbCur = (kt & 1) ? cb1 : cb0;
        if (kt + 1 < 32) {
            float* cbNext = (kt & 1) ? cb0 : cb1;
            load_cb_tile(cbNext, kt + 1, tid);
            cp_commit();
            cp_wait1();
        } else {
            cp_wait0();
        }
        __syncthreads();

        u64 aE[2][4], aO[2][4];
#pragma unroll
        for (int i = 0; i < 2; i++)
#pragma unroll
            for (int j = 0; j < 4; j++) { aE[i][j] = 0ull; aO[i][j] = 0ull; }

        const char* cptr = (const char*)cbCur + tx * 32;   // this thread's 8 codes
#pragma unroll 8
        for (int d = 0; d < 128; d++) {
            ulonglong2 X  = *(const ulonglong2*)(xptr + d * 256);        // (t0,t1),(t2,t3)
            ulonglong2 C0 = *(const ulonglong2*)(cptr + d * 528);        // (c0,c1),(c2,c3)
            ulonglong2 C1 = *(const ulonglong2*)(cptr + d * 528 + 16);   // (c4,c5),(c6,c7)
            u64 XS0 = swap_pair(X.x);                                    // (t1,t0)
            u64 XS1 = swap_pair(X.y);                                    // (t3,t2)
            ffma2(aE[0][0], X.x, C0.x);  ffma2(aE[0][1], X.x, C0.y);
            ffma2(aE[0][2], X.x, C1.x);  ffma2(aE[0][3], X.x, C1.y);
            ffma2(aE[1][0], X.y, C0.x);  ffma2(aE[1][1], X.y, C0.y);
            ffma2(aE[1][2], X.y, C1.x);  ffma2(aE[1][3], X.y, C1.y);
            ffma2(aO[0][0], XS0, C0.x);  ffma2(aO[0][1], XS0, C0.y);
            ffma2(aO[0][2], XS0, C1.x);  ffma2(aO[0][3], XS0, C1.y);
            ffma2(aO[1][0], XS1, C0.x);  ffma2(aO[1][1], XS1, C0.y);
            ffma2(aO[1][2], XS1, C1.x);  ffma2(aO[1][3], XS1, C1.y);
        }

        // running argmax; codes ascend -> strict > keeps first occurrence
        int cbase = kt * 128 + tx * 8;
#pragma unroll
        for (int j = 0; j < 4; j++) {
            int c0 = cbase + 2 * j, c1 = c0 + 1;
#pragma unroll
            for (int i = 0; i < 2; i++) {
                float e0, e1, o0, o1;
                unpack2(e0, e1, aE[i][j]);   // (S[t2i][c0], S[t2i+1][c1])
                unpack2(o0, o1, aO[i][j]);   // (S[t2i+1][c0], S[t2i][c1])
                int t0 = 2 * i, t1 = 2 * i + 1;
                if (e0 > best[t0]) { best[t0] = e0; bidx[t0] = c0; }
                if (o1 > best[t0]) { best[t0] = o1; bidx[t0] = c1; }
                if (o0 > best[t1]) { best[t1] = o0; bidx[t1] = c0; }
                if (e1 > best[t1]) { best[t1] = e1; bidx[t1] = c1; }
            }
        }
        __syncthreads();   // protect cbCur from next iteration's prefetch
    }

    // ---- cross-thread argmax reduction (reuse cb0 smem) ----
    float* redv = cb0;                         // [64][17]
    int* redi = (int*)(cb0 + 64 * 17);
#pragma unroll
    for (int i = 0; i < 4; i++) {
        int r = ty * 4 + i;
        redv[r * 17 + tx] = best[i];
        redi[r * 17 + tx] = bidx[i];
    }
    __syncthreads();

    int* s_idx = (int*)xs;                     // [64]
    float* s_val = xs + 64;
    if (tid < 64) {
        float bv = redv[tid * 17];
        int bi = redi[tid * 17];
#pragma unroll
        for (int j = 1; j < 16; j++) {
            float v = redv[tid * 17 + j];
            int ii = redi[tid * 17 + j];
            if (v > bv || (v == bv && ii < bi)) { bv = v; bi = ii; }
        }
        s_idx[tid] = bi;
        s_val[tid] = bv;
    }
    __syncthreads();

    // deterministic per-block loss partial
    if (tid < 64) {
        float v = s_val[tid];
#pragma unroll
        for (int o = 16; o; o >>= 1) v += __shfl_down_sync(0xffffffffu, v, o);
        if ((tid & 31) == 0) s_val[64 + (tid >> 5)] = v;
    }
    __syncthreads();
    if (tid == 0) g_blocksum[bid] = s_val[64] + s_val[65];

    // ---- write quantized output in [B, D, L] layout ----
    int b = bid >> 6, l0 = (bid & 63) * 64;
#pragma unroll
    for (int it = 0; it < 32; it++) {
        int e = it * 256 + tid;
        int t = e & 63, d = e >> 6;
        out[((size_t)(b * D_ + d)) * L_ + l0 + t] = g_cbn[(size_t)s_idx[t] * D_ + d];
    }

    // ---- last block finalizes the loss (deterministic fixed-order sums) ----
    __shared__ int s_last;
    if (tid == 0) {
        __threadfence();
        s_last = (atomicAdd(&g_count, 1u) == NBLK - 1);
    }
    __syncthreads();
    if (s_last) {
        __threadfence();
        float* red = xs;
        float sv = g_blocksum[tid] + g_blocksum[tid + 256] +
                   g_blocksum[tid + 512] + g_blocksum[tid + 768];
        red[tid] = sv;
        __syncthreads();
        for (int o = 128; o; o >>= 1) {
            if (tid < o) red[tid] += red[tid + o];
            __syncthreads();
        }
        if (tid == 0) out[out_size - 1] = 2.0f - 2.0f * red[0] / (float)N_;
    }
}

extern "C" void kernel_launch(void* const* d_in, const int* in_sizes, int n_in,
                              void* d_out, int out_size) {
    const float* x = (const float*)d_in[0];    // [16, 128, 4096] f32
    const float* cb = (const float*)d_in[1];   // [4096, 128] f32
    float* out = (float*)d_out;

    cudaFuncSetAttribute(vq_main_kernel,
                         cudaFuncAttributeMaxDynamicSharedMemorySize, SMEM_MAIN);

    prep_kernel<<<1536, 256>>>(x, cb);
    vq_main_kernel<<<NBLK, 256, SMEM_MAIN>>>(out, out_size);
}

// round 10
// speedup vs baseline: 5.4146x; 5.0532x over previous
#include <cuda_runtime.h>
#include <cuda_bf16.h>

#define D_ 128
#define L_ 4096
#define K_ 4096
#define N_ 65536
#define NTILE 512            // main CTAs: 128 tokens each
#define NCHUNK 32            // 32 chunks of 128 codes
#define MARGIN 0.016f        // 2 * bf16 dot error bound (2^-7) + slop
#define LCAP 12288
#define L2CAP 1024

typedef unsigned long long u64;
typedef unsigned int u32;

// ---- scratch (static device globals; no allocation) ----
__device__ __align__(16) float g_xn[(size_t)N_ * D_];              // normalized x fp32 [tok][d]
__device__ __align__(16) __nv_bfloat16 g_xb[(size_t)N_ * D_];      // bf16 copy
__device__ __align__(16) float g_cbn[(size_t)K_ * D_];             // normalized cb fp32 [code][d]
__device__ __align__(16) __nv_bfloat16 g_cbb[(size_t)K_ * D_];     // bf16 copy
__device__ float g_blocksum[NTILE];
__device__ u32 g_count;

// ---- smem offsets (dynamic) ----
#define SA_OFF     0            // A tile 128 x 256B         (32768)
#define SB_OFF     32768        // B double buffer 2 x 32768 (65536)
#define LIST_OFF   98304        // u64 x LCAP                (98304)
#define RMAX_OFF   196608       // float x 128
#define WIN_OFF    197120       // u64 x 128
#define LIST2_OFF  198144       // u32 x L2CAP               (4096)
#define CNT_OFF    202240
#define CNT2_OFF   202244
#define FLAG_OFF   202248
#define LP_OFF     202256       // 4 warp loss partials
#define SMEM_MAIN  202752

// ---- helpers ----
__device__ __forceinline__ u32 smem_u32(const void* p) {
    return (u32)__cvta_generic_to_shared(p);
}
__device__ __forceinline__ void cp16(u32 dst, const void* src) {
    asm volatile("cp.async.cg.shared.global [%0], [%1], 16;" :: "r"(dst), "l"(src) : "memory");
}
__device__ __forceinline__ void cp_commit() { asm volatile("cp.async.commit_group;" ::: "memory"); }
__device__ __forceinline__ void cp_wait1()  { asm volatile("cp.async.wait_group 1;" ::: "memory"); }
__device__ __forceinline__ void cp_wait0()  { asm volatile("cp.async.wait_group 0;" ::: "memory"); }

__device__ __forceinline__ void ldsm4(u32& r0, u32& r1, u32& r2, u32& r3, u32 addr) {
    asm volatile("ldmatrix.sync.aligned.m8n8.x4.shared.b16 {%0,%1,%2,%3}, [%4];"
                 : "=r"(r0), "=r"(r1), "=r"(r2), "=r"(r3) : "r"(addr));
}
// B operand: [code][k] storage with k contiguous == col-major KxN.
// NON-trans ldmatrix with code-row addresses yields the exact b-fragment
// (lane = n*4 + k/2), same as the A side. (.trans was the R9 bug.)
__device__ __forceinline__ void ldsm2(u32& r0, u32& r1, u32 addr) {
    asm volatile("ldmatrix.sync.aligned.m8n8.x2.shared.b16 {%0,%1}, [%2];"
                 : "=r"(r0), "=r"(r1) : "r"(addr));
}
__device__ __forceinline__ void mma16816(float* c, u32 a0, u32 a1, u32 a2, u32 a3,
                                         u32 b0, u32 b1) {
    asm volatile(
        "mma.sync.aligned.m16n8k16.row.col.f32.bf16.bf16.f32 "
        "{%0,%1,%2,%3}, {%4,%5,%6,%7}, {%8,%9}, {%0,%1,%2,%3};"
        : "+f"(c[0]), "+f"(c[1]), "+f"(c[2]), "+f"(c[3])
        : "r"(a0), "r"(a1), "r"(a2), "r"(a3), "r"(b0), "r"(b1));
}

// monotonic float<->u32 order-preserving map
__device__ __forceinline__ u32 ford(u32 b) {
    return b ^ (((int)b >> 31) | 0x80000000u);
}
__device__ __forceinline__ float finv(u32 u) {
    u32 b = (u & 0x80000000u) ? (u ^ 0x80000000u) : ~u;
    return __uint_as_float(b);
}

// ================= kernel 1: prep =================
// blocks [0,512): normalize codebook (8 rows/block) -> g_cbn + g_cbb
// blocks [512,1536): transpose+normalize x (64 tokens/block) -> g_xn + g_xb
__global__ void prep_kernel(const float* __restrict__ x, const float* __restrict__ cb) {
    __shared__ float s[128][65];
    __shared__ float psum[4][64];
    __shared__ float sinv[64];
    int tid = threadIdx.x;
    int bid = blockIdx.x;
    if (bid == 0 && tid == 0) g_count = 0;

    if (bid < 512) {
        int wid = tid >> 5, lane = tid & 31;
        int row = bid * 8 + wid;
        float4 v = ((const float4*)(cb + (size_t)row * D_))[lane];
        float ss = v.x * v.x + v.y * v.y + v.z * v.z + v.w * v.w;
#pragma unroll
        for (int o = 16; o; o >>= 1) ss += __shfl_xor_sync(0xffffffffu, ss, o);
        float inv = 1.0f / fmaxf(sqrtf(ss), 1e-12f);
        float vv[4] = {v.x * inv, v.y * inv, v.z * inv, v.w * inv};
        ((float4*)(g_cbn + (size_t)row * D_))[lane] = make_float4(vv[0], vv[1], vv[2], vv[3]);
        int d0 = lane * 4;
#pragma unroll
        for (int j = 0; j < 4; j++)
            g_cbb[(size_t)row * D_ + d0 + j] = __float2bfloat16(vv[j]);
    } else {
        int xb = bid - 512;               // 0..1023, 64 tokens each
        int b = xb >> 6;
        int l0 = (xb & 63) * 64;
        int lq = tid & 15, drow = tid >> 4;
#pragma unroll
        for (int it = 0; it < 8; it++) {
            int d = it * 16 + drow;
            float4 v = *(const float4*)(x + ((size_t)(b * D_ + d)) * L_ + l0 + lq * 4);
            s[d][lq * 4 + 0] = v.x;
            s[d][lq * 4 + 1] = v.y;
            s[d][lq * 4 + 2] = v.z;
            s[d][lq * 4 + 3] = v.w;
        }
        __syncthreads();
        int t = tid & 63, g = tid >> 6;
        float p = 0.f;
#pragma unroll
        for (int dd = 0; dd < 32; dd++) { float v = s[g * 32 + dd][t]; p += v * v; }
        psum[g][t] = p;
        __syncthreads();
        if (tid < 64) {
            float n = sqrtf(psum[0][tid] + psum[1][tid] + psum[2][tid] + psum[3][tid]);
            sinv[tid] = 1.0f / fmaxf(n, 1e-12f);
        }
        __syncthreads();
        size_t n0 = (size_t)xb * 64;
#pragma unroll
        for (int it = 0; it < 32; it++) {
            int e = it * 256 + tid;
            int tt = e >> 7, d = e & 127;
            float v = s[d][tt] * sinv[tt];
            size_t idx = (n0 + tt) * D_ + d;
            g_xn[idx] = v;
            g_xb[idx] = __float2bfloat16(v);
        }
    }
}

// ================= kernel 2: HMMA GEMM + candidate filter + exact rescore =================
// CTA = 128 tokens x full 4096 codes. 8 warps, warp owns 16 token rows.
// A tile resident (128 x 128 bf16, xor-swizzled 16B blocks).
// B: 128-code chunks double buffered via cp.async.
__global__ __launch_bounds__(256, 1) void vq_hmma_kernel(float* __restrict__ out, int out_size) {
    extern __shared__ char sm[];
    u32 sb = smem_u32(sm);
    u64* list   = (u64*)(sm + LIST_OFF);
    float* rmax = (float*)(sm + RMAX_OFF);
    u64* winner = (u64*)(sm + WIN_OFF);
    u32* list2  = (u32*)(sm + LIST2_OFF);
    u32* cnt    = (u32*)(sm + CNT_OFF);
    u32* cnt2   = (u32*)(sm + CNT2_OFF);

    int tid = threadIdx.x, wid = tid >> 5, lane = tid & 31;
    int bid = blockIdx.x;
    if (tid < 128) winner[tid] = 0ull;
    if (tid == 0) { *cnt = 0; *cnt2 = 0; }

    // ---- load A tile + B chunk 0 (xor-swizzled: block c of row r at c^(r&15)) ----
#pragma unroll
    for (int i = 0; i < 8; i++) {
        int e = i * 256 + tid;
        int r = e >> 4, c = e & 15;
        cp16(sb + SA_OFF + r * 256 + ((c ^ (r & 15)) * 16),
             (const char*)g_xb + ((size_t)(bid * 128 + r)) * 256 + c * 16);
    }
#pragma unroll
    for (int i = 0; i < 8; i++) {
        int e = i * 256 + tid;
        int r = e >> 4, c = e & 15;
        cp16(sb + SB_OFF + r * 256 + ((c ^ (r & 15)) * 16),
             (const char*)g_cbb + ((size_t)r) * 256 + c * 16);
    }
    cp_commit();
    cp_wait0();
    __syncthreads();

    float runmax0 = -2.0f, runmax1 = -2.0f;    // rows wid*16+g and +8
    int g4 = lane >> 2, q4 = lane & 3;
    u32 aBase = sb + SA_OFF + (wid * 16) * 256;

    for (int ck = 0; ck < NCHUNK; ck++) {
        if (ck + 1 < NCHUNK) {
            u32 nb = sb + SB_OFF + ((ck + 1) & 1) * 32768;
#pragma unroll
            for (int i = 0; i < 8; i++) {
                int e = i * 256 + tid;
                int r = e >> 4, c = e & 15;
                cp16(nb + r * 256 + ((c ^ (r & 15)) * 16),
                     (const char*)g_cbb + ((size_t)((ck + 1) * 128 + r)) * 256 + c * 16);
            }
            cp_commit();
            cp_wait1();
        } else {
            cp_wait0();
        }
        __syncthreads();

        u32 bBase = sb + SB_OFF + (ck & 1) * 32768;
        float acc[16][4];
#pragma unroll
        for (int j = 0; j < 16; j++) {
            acc[j][0] = 0.f; acc[j][1] = 0.f; acc[j][2] = 0.f; acc[j][3] = 0.f;
        }

#pragma unroll
        for (int kk = 0; kk < 8; kk++) {
            // A frag: rows (lane&7)+((lane>>3)&1)*8, block 2kk+(lane>>4)
            int ar = (lane & 7) + ((lane >> 3) & 1) * 8;
            int ac = 2 * kk + (lane >> 4);
            u32 a0, a1, a2, a3;
            ldsm4(a0, a1, a2, a3, aBase + ar * 256 + ((ac ^ ((wid * 16 + ar) & 15)) * 16));
#pragma unroll
            for (int j = 0; j < 16; j++) {
                int br = j * 8 + (lane & 7);
                int bc = 2 * kk + ((lane >> 3) & 1);
                u32 b0, b1;
                ldsm2(b0, b1, bBase + br * 256 + ((bc ^ (br & 15)) * 16));
                mma16816(acc[j], a0, a1, a2, a3, b0, b1);
            }
        }

        // ---- epilogue: chunk max -> running max -> candidate append ----
        float m0 = acc[0][0], m1 = acc[0][2];
#pragma unroll
        for (int j = 0; j < 16; j++) {
            m0 = fmaxf(m0, fmaxf(acc[j][0], acc[j][1]));
            m1 = fmaxf(m1, fmaxf(acc[j][2], acc[j][3]));
        }
        m0 = fmaxf(m0, __shfl_xor_sync(0xffffffffu, m0, 1));
        m0 = fmaxf(m0, __shfl_xor_sync(0xffffffffu, m0, 2));
        m1 = fmaxf(m1, __shfl_xor_sync(0xffffffffu, m1, 1));
        m1 = fmaxf(m1, __shfl_xor_sync(0xffffffffu, m1, 2));
        runmax0 = fmaxf(runmax0, m0);
        runmax1 = fmaxf(runmax1, m1);
        float thr0 = runmax0 - MARGIN, thr1 = runmax1 - MARGIN;
        int tok0 = wid * 16 + g4, tok1 = tok0 + 8;
        int colb = ck * 128 + q4 * 2;
#pragma unroll
        for (int j = 0; j < 16; j++) {
            int c0 = colb + j * 8, c1 = c0 + 1;
            if (acc[j][0] >= thr0) {
                u32 p = atomicAdd(cnt, 1u);
                if (p < LCAP) list[p] = ((u64)__float_as_uint(acc[j][0]) << 32) | (u32)(tok0 << 12) | c0;
            }
            if (acc[j][1] >= thr0) {
                u32 p = atomicAdd(cnt, 1u);
                if (p < LCAP) list[p] = ((u64)__float_as_uint(acc[j][1]) << 32) | (u32)(tok0 << 12) | c1;
            }
            if (acc[j][2] >= thr1) {
                u32 p = atomicAdd(cnt, 1u);
                if (p < LCAP) list[p] = ((u64)__float_as_uint(acc[j][2]) << 32) | (u32)(tok1 << 12) | c0;
            }
            if (acc[j][3] >= thr1) {
                u32 p = atomicAdd(cnt, 1u);
                if (p < LCAP) list[p] = ((u64)__float_as_uint(acc[j][3]) << 32) | (u32)(tok1 << 12) | c1;
            }
        }
        __syncthreads();   // reads of B buf done before next prefetch overwrites
    }

    // ---- final per-token max to smem ----
    rmax[wid * 16 + g4] = runmax0;          // 4 lanes write identical value
    rmax[wid * 16 + 8 + g4] = runmax1;
    __syncthreads();

    // ---- filter shortlist against final max ----
    int c1n = min(*cnt, (u32)LCAP);
    for (int i = tid; i < c1n; i += 256) {
        u64 e = list[i];
        float s = __uint_as_float((u32)(e >> 32));
        int tok = (int)((e >> 12) & 127);
        if (s >= rmax[tok] - MARGIN) {
            u32 p = atomicAdd(cnt2, 1u);
            if (p < L2CAP) list2[p] = (u32)(e & 0x7FFFFu);
        }
    }
    __syncthreads();

    // ---- exact fp32 rescore of survivors (one warp per entry) ----
    int c2n = min(*cnt2, (u32)L2CAP);
    for (int i = wid; i < c2n; i += 8) {
        u32 m = list2[i];
        int tok = m >> 12, code = m & 4095;
        float4 xv = ((const float4*)(g_xn + ((size_t)(bid * 128 + tok)) * D_))[lane];
        float4 cv = ((const float4*)(g_cbn + (size_t)code * D_))[lane];
        float d = xv.x * cv.x + xv.y * cv.y + xv.z * cv.z + xv.w * cv.w;
#pragma unroll
        for (int o = 16; o; o >>= 1) d += __shfl_xor_sync(0xffffffffu, d, o);
        if (lane == 0) {
            u64 key = ((u64)ford(__float_as_uint(d)) << 32) | (u32)(4095 - code);
            atomicMax(winner + tok, key);
        }
    }
    __syncthreads();

    // ---- loss partial + output ----
    if (tid < 128) {
        u64 k = winner[tid];
        float sc = finv((u32)(k >> 32));
        rmax[tid] = sc;                      // reuse as exact-score buffer
    }
    __syncthreads();
    if (wid < 4) {
        float v = rmax[tid];
#pragma unroll
        for (int o = 16; o; o >>= 1) v += __shfl_down_sync(0xffffffffu, v, o);
        if (lane == 0) ((float*)(sm + LP_OFF))[wid] = v;
    }
    __syncthreads();
    if (tid == 0) {
        float* pp = (float*)(sm + LP_OFF);
        g_blocksum[bid] = (pp[0] + pp[1]) + (pp[2] + pp[3]);
    }
    if (tid < 128) {
        int code = 4095 - (int)(winner[tid] & 0xFFFu);
        int n = bid * 128 + tid;
        int b = n >> 12, l = n & 4095;
        const float* crow = g_cbn + (size_t)code * D_;
        float* obase = out + ((size_t)(b * D_)) * L_ + l;
#pragma unroll 4
        for (int d = 0; d < 128; d++) obase[(size_t)d * L_] = crow[d];
    }

    // ---- last block finalizes loss ----
    int* flag = (int*)(sm + FLAG_OFF);
    if (tid == 0) {
        __threadfence();
        *flag = (atomicAdd(&g_count, 1u) == NTILE - 1);
    }
    __syncthreads();
    if (*flag) {
        __threadfence();
        float* red = (float*)(sm + SA_OFF);
        red[tid] = g_blocksum[tid] + g_blocksum[tid + 256];
        __syncthreads();
        for (int o = 128; o; o >>= 1) {
            if (tid < o) red[tid] += red[tid + o];
            __syncthreads();
        }
        if (tid == 0) out[out_size - 1] = 2.0f - 2.0f * red[0] / (float)N_;
    }
}

extern "C" void kernel_launch(void* const* d_in, const int* in_sizes, int n_in,
                              void* d_out, int out_size) {
    const float* x = (const float*)d_in[0];    // [16, 128, 4096] f32
    const float* cb = (const float*)d_in[1];   // [4096, 128] f32
    float* out = (float*)d_out;

    cudaFuncSetAttribute(vq_hmma_kernel,
                         cudaFuncAttributeMaxDynamicSharedMemorySize, SMEM_MAIN);

    prep_kernel<<<1536, 256>>>(x, cb);
    vq_hmma_kernel<<<NTILE, 256, SMEM_MAIN>>>(out, out_size);
}

// round 12
// speedup vs baseline: 8.0717x; 1.4907x over previous
#include <cuda_runtime.h>
#include <cuda_bf16.h>

#define D_ 128
#define L_ 4096
#define K_ 4096
#define N_ 65536
#define NTILE 512            // main CTAs: 128 tokens each
#define NCHUNK 64            // 64 chunks of 64 codes
#define MARGIN 0.016f        // 2 * bf16 dot error bound (2^-7) + slop
#define LCAP 8192
#define L2CAP 1024

typedef unsigned long long u64;
typedef unsigned int u32;

// ---- scratch (static device globals; no allocation) ----
__device__ __align__(16) float g_xn[(size_t)N_ * D_];              // normalized x fp32 [tok][d]
__device__ __align__(16) __nv_bfloat16 g_xb[(size_t)N_ * D_];      // bf16 copy
__device__ __align__(16) float g_cbn[(size_t)K_ * D_];             // normalized cb fp32 [code][d]
__device__ __align__(16) __nv_bfloat16 g_cbb[(size_t)K_ * D_];     // bf16 copy
__device__ float g_blocksum[NTILE];
__device__ u32 g_count;

// ---- smem offsets (dynamic). A prologue tile (32KB) overlaps the list (64KB).
#define SA_OFF     0
#define LIST_OFF   0            // u64 x LCAP = 65536
#define SB_OFF     65536        // B double buffer 2 x 16384 = 32768
#define RMAX_OFF   98304        // float x 128
#define WIN_OFF    98816        // u64 x 128
#define LIST2_OFF  99840        // u32 x L2CAP = 4096
#define CNT_OFF    103936
#define CNT2_OFF   103940
#define FLAG_OFF   103944
#define LP_OFF     103952       // 4 warp loss partials
#define SMEM_MAIN  104960

// ---- helpers ----
__device__ __forceinline__ u32 smem_u32(const void* p) {
    return (u32)__cvta_generic_to_shared(p);
}
__device__ __forceinline__ void cp16(u32 dst, const void* src) {
    asm volatile("cp.async.cg.shared.global [%0], [%1], 16;" :: "r"(dst), "l"(src) : "memory");
}
__device__ __forceinline__ void cp_commit() { asm volatile("cp.async.commit_group;" ::: "memory"); }
__device__ __forceinline__ void cp_wait1()  { asm volatile("cp.async.wait_group 1;" ::: "memory"); }
__device__ __forceinline__ void cp_wait0()  { asm volatile("cp.async.wait_group 0;" ::: "memory"); }

__device__ __forceinline__ void ldsm4(u32& r0, u32& r1, u32& r2, u32& r3, u32 addr) {
    asm volatile("ldmatrix.sync.aligned.m8n8.x4.shared.b16 {%0,%1,%2,%3}, [%4];"
                 : "=r"(r0), "=r"(r1), "=r"(r2), "=r"(r3) : "r"(addr));
}
__device__ __forceinline__ void mma16816(float* c, const u32* a, u32 b0, u32 b1) {
    asm volatile(
        "mma.sync.aligned.m16n8k16.row.col.f32.bf16.bf16.f32 "
        "{%0,%1,%2,%3}, {%4,%5,%6,%7}, {%8,%9}, {%0,%1,%2,%3};"
        : "+f"(c[0]), "+f"(c[1]), "+f"(c[2]), "+f"(c[3])
        : "r"(a[0]), "r"(a[1]), "r"(a[2]), "r"(a[3]), "r"(b0), "r"(b1));
}

// monotonic float<->u32 order-preserving map
__device__ __forceinline__ u32 ford(u32 b) {
    return b ^ (((int)b >> 31) | 0x80000000u);
}
__device__ __forceinline__ float finv(u32 u) {
    u32 b = (u & 0x80000000u) ? (u ^ 0x80000000u) : ~u;
    return __uint_as_float(b);
}

// ================= kernel 1: prep =================
__global__ void prep_kernel(const float* __restrict__ x, const float* __restrict__ cb) {
    __shared__ float s[128][65];
    __shared__ float psum[4][64];
    __shared__ float sinv[64];
    int tid = threadIdx.x;
    int bid = blockIdx.x;
    if (bid == 0 && tid == 0) g_count = 0;

    if (bid < 512) {
        int wid = tid >> 5, lane = tid & 31;
        int row = bid * 8 + wid;
        float4 v = ((const float4*)(cb + (size_t)row * D_))[lane];
        float ss = v.x * v.x + v.y * v.y + v.z * v.z + v.w * v.w;
#pragma unroll
        for (int o = 16; o; o >>= 1) ss += __shfl_xor_sync(0xffffffffu, ss, o);
        float inv = 1.0f / fmaxf(sqrtf(ss), 1e-12f);
        float vv[4] = {v.x * inv, v.y * inv, v.z * inv, v.w * inv};
        ((float4*)(g_cbn + (size_t)row * D_))[lane] = make_float4(vv[0], vv[1], vv[2], vv[3]);
        int d0 = lane * 4;
#pragma unroll
        for (int j = 0; j < 4; j++)
            g_cbb[(size_t)row * D_ + d0 + j] = __float2bfloat16(vv[j]);
    } else {
        int xb = bid - 512;
        int b = xb >> 6;
        int l0 = (xb & 63) * 64;
        int lq = tid & 15, drow = tid >> 4;
#pragma unroll
        for (int it = 0; it < 8; it++) {
            int d = it * 16 + drow;
            float4 v = *(const float4*)(x + ((size_t)(b * D_ + d)) * L_ + l0 + lq * 4);
            s[d][lq * 4 + 0] = v.x;
            s[d][lq * 4 + 1] = v.y;
            s[d][lq * 4 + 2] = v.z;
            s[d][lq * 4 + 3] = v.w;
        }
        __syncthreads();
        int t = tid & 63, g = tid >> 6;
        float p = 0.f;
#pragma unroll
        for (int dd = 0; dd < 32; dd++) { float v = s[g * 32 + dd][t]; p += v * v; }
        psum[g][t] = p;
        __syncthreads();
        if (tid < 64) {
            float n = sqrtf(psum[0][tid] + psum[1][tid] + psum[2][tid] + psum[3][tid]);
            sinv[tid] = 1.0f / fmaxf(n, 1e-12f);
        }
        __syncthreads();
        size_t n0 = (size_t)xb * 64;
#pragma unroll
        for (int it = 0; it < 32; it++) {
            int e = it * 256 + tid;
            int tt = e >> 7, d = e & 127;
            float v = s[d][tt] * sinv[tt];
            size_t idx = (n0 + tt) * D_ + d;
            g_xn[idx] = v;
            g_xb[idx] = __float2bfloat16(v);
        }
    }
}

// ================= kernel 2: HMMA GEMM + candidate filter + exact rescore =================
// CTA = 128 tokens x full 4096 codes, 256 threads (8 warps x 16 tokens), 2 CTAs/SM.
// A fragments register-resident (loaded once). B: 64-code chunks, double buffered,
// fetched with full-width ldsm4 (two 8-code n-blocks per instruction).
__global__ __launch_bounds__(256, 2) void vq_hmma_kernel(float* __restrict__ out, int out_size) {
    extern __shared__ char sm[];
    u32 sb = smem_u32(sm);
    u64* list   = (u64*)(sm + LIST_OFF);
    float* rmax = (float*)(sm + RMAX_OFF);
    u64* winner = (u64*)(sm + WIN_OFF);
    u32* list2  = (u32*)(sm + LIST2_OFF);
    u32* cnt    = (u32*)(sm + CNT_OFF);
    u32* cnt2   = (u32*)(sm + CNT2_OFF);

    int tid = threadIdx.x, wid = tid >> 5, lane = tid & 31;
    int bid = blockIdx.x;
    if (tid < 128) winner[tid] = 0ull;
    if (tid == 0) { *cnt = 0; *cnt2 = 0; }

    // ---- prologue: A tile (into list region, transient) + B chunk 0 ----
#pragma unroll
    for (int i = 0; i < 8; i++) {
        int e = i * 256 + tid;
        int r = e >> 4, c = e & 15;
        cp16(sb + SA_OFF + r * 256 + ((c ^ (r & 15)) * 16),
             (const char*)g_xb + ((size_t)(bid * 128 + r)) * 256 + c * 16);
    }
#pragma unroll
    for (int i = 0; i < 4; i++) {           // 64 codes x 256B = 16KB
        int e = i * 256 + tid;
        int r = e >> 4, c = e & 15;
        cp16(sb + SB_OFF + r * 256 + ((c ^ (r & 15)) * 16),
             (const char*)g_cbb + ((size_t)r) * 256 + c * 16);
    }
    cp_commit();
    cp_wait0();
    __syncthreads();

    // ---- A fragments -> registers (once) ----
    u32 a[8][4];
    {
        int ar = (lane & 7) + ((lane >> 3) & 1) * 8;
        int row = wid * 16 + ar;
#pragma unroll
        for (int kk = 0; kk < 8; kk++) {
            int ac = 2 * kk + (lane >> 4);
            ldsm4(a[kk][0], a[kk][1], a[kk][2], a[kk][3],
                  sb + SA_OFF + row * 256 + ((ac ^ (row & 15)) * 16));
        }
    }
    __syncthreads();    // all warps done reading A region before list reuse

    float runmax0 = -2.0f, runmax1 = -2.0f;
    int g4 = lane >> 2, q4 = lane & 3;
    // B ldsm4 lane-address precompute: m0/m1 = j0 block, m2/m3 = j0+1 block
    int rowInPair = ((lane >> 4) << 3) + (lane & 7);   // 0..15
    int half = (lane >> 3) & 1;
    u32 bLane = rowInPair * 256;                       // + ((2kk+half)^rowInPair)*16

    for (int ck = 0; ck < NCHUNK; ck++) {
        if (ck + 1 < NCHUNK) {
            u32 nb = sb + SB_OFF + ((ck + 1) & 1) * 16384;
#pragma unroll
            for (int i = 0; i < 4; i++) {
                int e = i * 256 + tid;
                int r = e >> 4, c = e & 15;
                cp16(nb + r * 256 + ((c ^ (r & 15)) * 16),
                     (const char*)g_cbb + ((size_t)((ck + 1) * 64 + r)) * 256 + c * 16);
            }
            cp_commit();
            cp_wait1();
        } else {
            cp_wait0();
        }
        __syncthreads();

        u32 bBase = sb + SB_OFF + (ck & 1) * 16384 + bLane;
        float acc[8][4];
#pragma unroll
        for (int j = 0; j < 8; j++) {
            acc[j][0] = 0.f; acc[j][1] = 0.f; acc[j][2] = 0.f; acc[j][3] = 0.f;
        }

#pragma unroll
        for (int kk = 0; kk < 8; kk++) {
            u32 swz = ((u32)(2 * kk + half) ^ (u32)rowInPair) * 16;
#pragma unroll
            for (int j0 = 0; j0 < 8; j0 += 2) {
                u32 b0, b1, b2, b3;
                ldsm4(b0, b1, b2, b3, bBase + j0 * 2048 + swz);
                mma16816(acc[j0], a[kk], b0, b1);
                mma16816(acc[j0 + 1], a[kk], b2, b3);
            }
        }

        // ---- epilogue: chunk max -> running max -> candidate append ----
        float m0 = acc[0][0], m1 = acc[0][2];
#pragma unroll
        for (int j = 0; j < 8; j++) {
            m0 = fmaxf(m0, fmaxf(acc[j][0], acc[j][1]));
            m1 = fmaxf(m1, fmaxf(acc[j][2], acc[j][3]));
        }
        m0 = fmaxf(m0, __shfl_xor_sync(0xffffffffu, m0, 1));
        m0 = fmaxf(m0, __shfl_xor_sync(0xffffffffu, m0, 2));
        m1 = fmaxf(m1, __shfl_xor_sync(0xffffffffu, m1, 1));
        m1 = fmaxf(m1, __shfl_xor_sync(0xffffffffu, m1, 2));
        runmax0 = fmaxf(runmax0, m0);
        runmax1 = fmaxf(runmax1, m1);
        float thr0 = runmax0 - MARGIN, thr1 = runmax1 - MARGIN;
        int tok0 = wid * 16 + g4, tok1 = tok0 + 8;
        int colb = ck * 64 + q4 * 2;
#pragma unroll
        for (int j = 0; j < 8; j++) {
            int c0 = colb + j * 8, c1 = c0 + 1;
            if (acc[j][0] >= thr0) {
                u32 p = atomicAdd(cnt, 1u);
                if (p < LCAP) list[p] = ((u64)__float_as_uint(acc[j][0]) << 32) | (u32)(tok0 << 12) | c0;
            }
            if (acc[j][1] >= thr0) {
                u32 p = atomicAdd(cnt, 1u);
                if (p < LCAP) list[p] = ((u64)__float_as_uint(acc[j][1]) << 32) | (u32)(tok0 << 12) | c1;
            }
            if (acc[j][2] >= thr1) {
                u32 p = atomicAdd(cnt, 1u);
                if (p < LCAP) list[p] = ((u64)__float_as_uint(acc[j][2]) << 32) | (u32)(tok1 << 12) | c0;
            }
            if (acc[j][3] >= thr1) {
                u32 p = atomicAdd(cnt, 1u);
                if (p < LCAP) list[p] = ((u64)__float_as_uint(acc[j][3]) << 32) | (u32)(tok1 << 12) | c1;
            }
        }
        __syncthreads();   // reads of B buf done before next prefetch overwrites
    }

    // ---- final per-token max to smem ----
    rmax[wid * 16 + g4] = runmax0;
    rmax[wid * 16 + 8 + g4] = runmax1;
    __syncthreads();

    // ---- filter shortlist against final max ----
    int c1n = min(*cnt, (u32)LCAP);
    for (int i = tid; i < c1n; i += 256) {
        u64 e = list[i];
        float s = __uint_as_float((u32)(e >> 32));
        int tok = (int)((e >> 12) & 127);
        if (s >= rmax[tok] - MARGIN) {
            u32 p = atomicAdd(cnt2, 1u);
            if (p < L2CAP) list2[p] = (u32)(e & 0x7FFFFu);
        }
    }
    __syncthreads();

    // ---- exact fp32 rescore of survivors (one warp per entry) ----
    int c2n = min(*cnt2, (u32)L2CAP);
    for (int i = wid; i < c2n; i += 8) {
        u32 m = list2[i];
        int tok = m >> 12, code = m & 4095;
        float4 xv = ((const float4*)(g_xn + ((size_t)(bid * 128 + tok)) * D_))[lane];
        float4 cv = ((const float4*)(g_cbn + (size_t)code * D_))[lane];
        float d = xv.x * cv.x + xv.y * cv.y + xv.z * cv.z + xv.w * cv.w;
#pragma unroll
        for (int o = 16; o; o >>= 1) d += __shfl_xor_sync(0xffffffffu, d, o);
        if (lane == 0) {
            u64 key = ((u64)ford(__float_as_uint(d)) << 32) | (u32)(4095 - code);
            atomicMax(winner + tok, key);
        }
    }
    __syncthreads();

    // ---- loss partial + output ----
    if (tid < 128) {
        u64 k = winner[tid];
        rmax[tid] = finv((u32)(k >> 32));
    }
    __syncthreads();
    if (wid < 4) {
        float v = rmax[tid];
#pragma unroll
        for (int o = 16; o; o >>= 1) v += __shfl_down_sync(0xffffffffu, v, o);
        if (lane == 0) ((float*)(sm + LP_OFF))[wid] = v;
    }
    __syncthreads();
    if (tid == 0) {
        float* pp = (float*)(sm + LP_OFF);
        g_blocksum[bid] = (pp[0] + pp[1]) + (pp[2] + pp[3]);
    }
    if (tid < 128) {
        int code = 4095 - (int)(winner[tid] & 0xFFFu);
        int n = bid * 128 + tid;
        int b = n >> 12, l = n & 4095;
        const float* crow = g_cbn + (size_t)code * D_;
        float* obase = out + ((size_t)(b * D_)) * L_ + l;
#pragma unroll 4
        for (int d = 0; d < 128; d++) obase[(size_t)d * L_] = crow[d];
    }

    // ---- last block finalizes loss ----
    int* flag = (int*)(sm + FLAG_OFF);
    if (tid == 0) {
        __threadfence();
        *flag = (atomicAdd(&g_count, 1u) == NTILE - 1);
    }
    __syncthreads();
    if (*flag) {
        __threadfence();
        float* red = (float*)(sm + SB_OFF);
        red[tid] = g_blocksum[tid] + g_blocksum[tid + 256];
        __syncthreads();
        for (int o = 128; o; o >>= 1) {
            if (tid < o) red[tid] += red[tid + o];
            __syncthreads();
        }
        if (tid == 0) out[out_size - 1] = 2.0f - 2.0f * red[0] / (float)N_;
    }
}

extern "C" void kernel_launch(void* const* d_in, const int* in_sizes, int n_in,
                              void* d_out, int out_size) {
    const float* x = (const float*)d_in[0];    // [16, 128, 4096] f32
    const float* cb = (const float*)d_in[1];   // [4096, 128] f32
    float* out = (float*)d_out;

    cudaFuncSetAttribute(vq_hmma_kernel,
                         cudaFuncAttributeMaxDynamicSharedMemorySize, SMEM_MAIN);

    prep_kernel<<<1536, 256>>>(x, cb);
    vq_hmma_kernel<<<NTILE, 256, SMEM_MAIN>>>(out, out_size);
}